// round 11
// baseline (speedup 1.0000x reference)
#include <cuda_runtime.h>

// QPSolver: N=32, M=64, BS=512, ITERS=1000, ALPHA=BETA=1
// Out layout (float32): Xs (512,1001,128) then primal_sols (512,1001,32).

#define BSZ   512
#define NDIM  32
#define MDIM  64
#define ITERS 1000

typedef unsigned long long ull;

__device__ __align__(16) float gD[MDIM * MDIM];      // D = H P^-1 H^T
__device__ __align__(16) float gHinv[NDIM * MDIM];   // pinv(H) (32x64)
__device__ __align__(16) float gWq[NDIM * MDIM];     // P^-1 H^T (32x64)
__device__ float gC;                                 // 1/lambda_max(D)

#define FMA2(acc, x, y) asm("fma.rn.f32x2 %0,%1,%2,%0;" : "+l"(acc) : "l"(x), "l"(y))

__device__ __forceinline__ float pairsum2(ull a, ull b) {
    ull s; asm("add.rn.f32x2 %0,%1,%2;" : "=l"(s) : "l"(a), "l"(b));
    unsigned lo, hi;
    asm("mov.b64 {%0,%1},%2;" : "=r"(lo), "=r"(hi) : "l"(s));
    return __uint_as_float(lo) + __uint_as_float(hi);
}
__device__ __forceinline__ float red8(ull* a) {
    ull s0, s1, s2, s3, t0, t1, s;
    asm("add.rn.f32x2 %0,%1,%2;" : "=l"(s0) : "l"(a[0]), "l"(a[1]));
    asm("add.rn.f32x2 %0,%1,%2;" : "=l"(s1) : "l"(a[2]), "l"(a[3]));
    asm("add.rn.f32x2 %0,%1,%2;" : "=l"(s2) : "l"(a[4]), "l"(a[5]));
    asm("add.rn.f32x2 %0,%1,%2;" : "=l"(s3) : "l"(a[6]), "l"(a[7]));
    asm("add.rn.f32x2 %0,%1,%2;" : "=l"(t0) : "l"(s0), "l"(s1));
    asm("add.rn.f32x2 %0,%1,%2;" : "=l"(t1) : "l"(s2), "l"(s3));
    asm("add.rn.f32x2 %0,%1,%2;" : "=l"(s)  : "l"(t0), "l"(t1));
    unsigned lo, hi;
    asm("mov.b64 {%0,%1},%2;" : "=r"(lo), "=r"(hi) : "l"(s));
    return __uint_as_float(lo) + __uint_as_float(hi);
}
__device__ __forceinline__ ull dup2(float a) {
    ull r; asm("mov.b64 %0,{%1,%1};" : "=l"(r) : "f"(a)); return r;
}

// ---------------------------------------------------------------------------
// Warp-scope Gauss-Jordan on a 32 x 96 system, rows in registers, shfl
// broadcast, NO barriers, NO pivoting (SPD left block). Lane l holds row l.
// ---------------------------------------------------------------------------
__device__ __forceinline__ void gj_warp(float a[96], int lane) {
    for (int c = 0; c < 32; c++) {
        float myc = 0.0f;
#pragma unroll
        for (int j = 0; j < 32; j++) if (j == c) myc = a[j];
        float pv = __shfl_sync(0xffffffffu, myc, c);
        float inv = 1.0f / pv;
        float f = myc * inv;
        bool isp = (lane == c);
#pragma unroll
        for (int j = 0; j < 96; j++) {
            float pr = __shfl_sync(0xffffffffu, a[j], c);
            a[j] = isp ? pr * inv : fmaf(-f, pr, a[j]);
        }
    }
}

// ---------------------------------------------------------------------------
// Setup (1 block, 256 threads).
// ---------------------------------------------------------------------------
__global__ void __launch_bounds__(256) setup_kernel(
    const float* __restrict__ P, const float* __restrict__ H)
{
    __shared__ __align__(16) float sm[8192];
    float* sH   = sm;          // 2048 (H, 64x32)
    float* sWq  = sm + 2048;   // 2048
    float* sD   = sm + 4096;   // 4096
    float* sTmp = sm;          // 4096 (aliases sH+sWq; both dead by squaring)
    __shared__ float sV[64];
    __shared__ double sT[8];

    int t = threadIdx.x, lane = t & 31, w = t >> 5;

    for (int i = t; i < 2048; i += 256) sH[i] = H[i];
    __syncthreads();

    if (w == 0) {
        float a[96];
#pragma unroll
        for (int j = 0; j < 32; j++) a[j] = P[lane * 32 + j];
#pragma unroll
        for (int j = 0; j < 64; j++) a[32 + j] = sH[j * 32 + lane];
        gj_warp(a, lane);
#pragma unroll
        for (int j = 0; j < 64; j++) {
            sWq[lane * 64 + j] = a[32 + j];
            gWq[lane * 64 + j] = a[32 + j];
        }
    } else if (w == 1) {
        ull acc[16];
#pragma unroll
        for (int j = 0; j < 16; j++) acc[j] = 0ull;
        for (int kk = 0; kk < 64; kk++) {
            ull hl = dup2(sH[kk * 32 + lane]);
            const ull* hr = (const ull*)(sH + kk * 32);
#pragma unroll
            for (int j = 0; j < 16; j++) FMA2(acc[j], hl, hr[j]);
        }
        float a[96];
#pragma unroll
        for (int j = 0; j < 16; j++) {
            unsigned lo, hi;
            asm("mov.b64 {%0,%1},%2;" : "=r"(lo), "=r"(hi) : "l"(acc[j]));
            a[2 * j] = __uint_as_float(lo);
            a[2 * j + 1] = __uint_as_float(hi);
        }
#pragma unroll
        for (int j = 0; j < 64; j++) a[32 + j] = sH[j * 32 + lane];
        gj_warp(a, lane);
#pragma unroll
        for (int j = 0; j < 64; j++) gHinv[lane * 64 + j] = a[32 + j];
    }
    __syncthreads();

    {
        int r = t >> 2, cb = (t & 3) * 8;
        ull acc[8];
#pragma unroll
        for (int j = 0; j < 8; j++) acc[j] = 0ull;
        for (int kk = 0; kk < 32; kk++) {
            ull ap = dup2(sH[r * 32 + kk]);
            const ull* rw = (const ull*)(sWq + kk * 64);
#pragma unroll
            for (int j = 0; j < 8; j++) FMA2(acc[j], ap, rw[cb + j]);
        }
        ull* drow = (ull*)(sD + r * 64);
        ull* grow = (ull*)(gD + r * 64);
#pragma unroll
        for (int j = 0; j < 8; j++) { drow[cb + j] = acc[j]; grow[cb + j] = acc[j]; }
    }
    __syncthreads();

    if (t < 32) {
        float v = sD[t * 65] + sD[(t + 32) * 65];
        for (int o = 16; o; o >>= 1) v += __shfl_xor_sync(0xffffffffu, v, o);
        if (t == 0) sT[0] = (double)v;
    }
    __syncthreads();
    {
        float inv = (float)(1.0 / sT[0]);
        for (int i = t; i < 4096; i += 256) sD[i] *= inv;
    }
    __syncthreads();
    for (int s = 1; s <= 5; s++) {
        {
            int r = t >> 2, cb = (t & 3) * 8;
            ull acc[8];
#pragma unroll
            for (int j = 0; j < 8; j++) acc[j] = 0ull;
            for (int kk = 0; kk < 64; kk++) {
                ull ap = dup2(sD[r * 64 + kk]);
                const ull* rw = (const ull*)(sD + kk * 64);
#pragma unroll
                for (int j = 0; j < 8; j++) FMA2(acc[j], ap, rw[cb + j]);
            }
            ull* trow = (ull*)(sTmp + r * 64);
#pragma unroll
            for (int j = 0; j < 8; j++) trow[cb + j] = acc[j];
        }
        __syncthreads();
        if (t < 32) {
            float v = sTmp[t * 65] + sTmp[(t + 32) * 65];
            for (int o = 16; o; o >>= 1) v += __shfl_xor_sync(0xffffffffu, v, o);
            if (t == 0) sT[s] = (double)v;
        }
        __syncthreads();
        {
            float inv = (float)(1.0 / sT[s]);
            for (int i = t; i < 4096; i += 256) sD[i] = sTmp[i] * inv;
        }
        __syncthreads();
    }

    if (w == 0) {
        ull d0[32], d1[32];
        const ull* sD2 = (const ull*)sD;
#pragma unroll
        for (int i = 0; i < 32; i++) {
            d0[i] = sD2[lane * 32 + i];
            d1[i] = sD2[(lane + 32) * 32 + i];
        }
        sV[lane] = 1.0f + 0.001f * (float)lane;
        sV[lane + 32] = 1.0f + 0.001f * (float)(lane + 32);
        __syncwarp();
        float v0 = sV[lane], v1 = sV[lane + 32], w0 = 0.0f, w1 = 0.0f;
        for (int it = 0; it <= 16; it++) {
            ull a0 = 0ull, a1 = 0ull, b0 = 0ull, b1 = 0ull;
            const ull* vv = (const ull*)sV;
#pragma unroll
            for (int i = 0; i < 32; i++) {
                ull vp = vv[i];
                if (i & 1) { FMA2(a1, d0[i], vp); FMA2(b1, d1[i], vp); }
                else       { FMA2(a0, d0[i], vp); FMA2(b0, d1[i], vp); }
            }
            w0 = pairsum2(a0, a1);
            w1 = pairsum2(b0, b1);
            if (it == 16) break;
            float m = fmaxf(fabsf(w0), fabsf(w1));
            for (int o = 16; o; o >>= 1) m = fmaxf(m, __shfl_xor_sync(0xffffffffu, m, o));
            float inv = 1.0f / m;
            v0 = w0 * inv; v1 = w1 * inv;
            sV[lane] = v0; sV[lane + 32] = v1;
            __syncwarp();
        }
        float num = v0 * w0 + v1 * w1;
        float den = v0 * v0 + v1 * v1;
        for (int o = 16; o; o >>= 1) {
            num += __shfl_xor_sync(0xffffffffu, num, o);
            den += __shfl_xor_sync(0xffffffffu, den, o);
        }
        if (lane == 0) {
            double lam = (double)num / (double)den;
            for (int s = 5; s >= 1; s--) lam = sqrt(sT[s] * lam);
            gC = (float)(1.0 / (sT[0] * lam));
        }
    }
}

// ---------------------------------------------------------------------------
// Fused solver+primal: 2 warps per row. Lane owns output r = lane + 32w.
//   y' = c*(D y + z) + mu ;  z' = relu(y + z - 2 y')
// Primal p(k) = Hinv z(k) - Hinv b is computed in the latency shadow with a
// 2-deep pipeline: iter k computes k-split partials of Hinv z(k-1) (both
// warps), and warp0 combines partials of z(k-2) -> STG p(k-2).
// ---------------------------------------------------------------------------
__global__ void __launch_bounds__(64) solve_kernel(
    const float* __restrict__ q, const float* __restrict__ b, float* __restrict__ out)
{
    __shared__ __align__(16) float sy[2][64];
    __shared__ __align__(16) float sz[2][64];
    __shared__ __align__(16) float sp[2][64];
    int lane = threadIdx.x & 31, w = threadIdx.x >> 5;
    int r = lane + 32 * w;
    int row = blockIdx.x;
    float c = gC;

    // D row r resident
    ull dR[32];
    const ull* gD2 = (const ull*)gD;
#pragma unroll
    for (int i = 0; i < 32; i++) dR[i] = gD2[r * 32 + i];

    // Hinv half-row for partials: output n = lane, k-range [32w, 32w+32)
    ull hv[16];
    const ull* gH2 = (const ull*)gHinv;
#pragma unroll
    for (int i = 0; i < 16; i++) hv[i] = gH2[lane * 32 + 16 * w + i];

    const float* qr = q + row * NDIM;
    const float* br = b + (size_t)row * MDIM;
    float mu = 0.0f;
#pragma unroll
    for (int i = 0; i < 32; i++) mu = fmaf(qr[i], gWq[i * 64 + r], mu);
    mu = c * (mu - br[r]);

    // hb (warp0 only, full Hinv row n = lane)
    float hb = 0.0f;
    if (w == 0) {
#pragma unroll
        for (int j = 0; j < 64; j++) hb = fmaf(gHinv[lane * 64 + j], br[j], hb);
    }

    float* Xp = out + (size_t)row * (ITERS + 1) * 128;
    float* Pp = out + (size_t)BSZ * (ITERS + 1) * 128 + (size_t)row * (ITERS + 1) * 32;

    // k = 0 outputs
    Xp[r] = 0.0f; Xp[64 + r] = 0.0f;
    if (w == 0) Pp[lane] = -hb;

    unsigned syb = (unsigned)__cvta_generic_to_shared(&sy[0][0]);
    unsigned szb = (unsigned)__cvta_generic_to_shared(&sz[0][0]);
    unsigned spb = (unsigned)__cvta_generic_to_shared(&sp[0][0]);
    unsigned r4 = 4u * (unsigned)r;

    asm volatile("st.shared.f32 [%0], %1;" :: "r"(syb + r4), "f"(0.0f));
    asm volatile("st.shared.f32 [%0], %1;" :: "r"(szb + r4), "f"(0.0f));
    __syncthreads();

    float y = 0.0f, z = 0.0f;
    float* xk = Xp + 128;

    for (int k = 1; k <= ITERS; k++) {
        unsigned rbo = ((unsigned)((k & 1) ^ 1)) << 8;   // read buf offset
        unsigned wbo = ((unsigned)(k & 1)) << 8;         // write buf offset
        // --- critical path: y-matvec ---
        ull acc[8];
#pragma unroll
        for (int i = 0; i < 8; i++) acc[i] = 0ull;
#pragma unroll
        for (int i = 0; i < 8; i++) {
            ull p0, p1;
            asm volatile("ld.shared.v2.b64 {%0,%1},[%2];"
                         : "=l"(p0), "=l"(p1) : "r"(syb + rbo + 32u * i));
            FMA2(acc[(2 * i) & 7], dR[4 * i + 0], p0);
            FMA2(acc[(2 * i + 1) & 7], dR[4 * i + 1], p1);
            ull p2, p3;
            asm volatile("ld.shared.v2.b64 {%0,%1},[%2];"
                         : "=l"(p2), "=l"(p3) : "r"(syb + rbo + 32u * i + 16u));
            FMA2(acc[(2 * i + 4) & 7], dR[4 * i + 2], p2);
            FMA2(acc[(2 * i + 5) & 7], dR[4 * i + 3], p3);
        }
        float wsum = red8(acc);
        float ny = fmaf(c, wsum + z, mu);
        asm volatile("st.shared.f32 [%0], %1;" :: "r"(syb + wbo + r4), "f"(ny));
        float nz = fmaxf(fmaf(-2.0f, ny, y + z), 0.0f);
        asm volatile("st.shared.f32 [%0], %1;" :: "r"(szb + wbo + r4), "f"(nz));
        y = ny; z = nz;
        xk[r] = y; xk[64 + r] = z;
        xk += 128;

        // --- shadow: partial of Hinv z(k-1) over this warp's k-half ---
        if (k >= 2) {
            ull pa0 = 0ull, pa1 = 0ull, pa2 = 0ull, pa3 = 0ull;
            unsigned zb = szb + rbo + ((unsigned)w << 7);
#pragma unroll
            for (int i = 0; i < 4; i++) {
                ull z0, z1;
                asm volatile("ld.shared.v2.b64 {%0,%1},[%2];"
                             : "=l"(z0), "=l"(z1) : "r"(zb + 32u * i));
                FMA2(pa0, hv[4 * i + 0], z0);
                FMA2(pa1, hv[4 * i + 1], z1);
                ull z2, z3;
                asm volatile("ld.shared.v2.b64 {%0,%1},[%2];"
                             : "=l"(z2), "=l"(z3) : "r"(zb + 32u * i + 16u));
                FMA2(pa2, hv[4 * i + 2], z2);
                FMA2(pa3, hv[4 * i + 3], z3);
            }
            ull q0, q1;
            asm("add.rn.f32x2 %0,%1,%2;" : "=l"(q0) : "l"(pa0), "l"(pa1));
            asm("add.rn.f32x2 %0,%1,%2;" : "=l"(q1) : "l"(pa2), "l"(pa3));
            float part = pairsum2(q0, q1);
            unsigned par1 = ((unsigned)((k - 1) & 1)) << 8;
            asm volatile("st.shared.f32 [%0], %1;" :: "r"(spb + par1 + r4), "f"(part));
        }
        // --- shadow: combine partials of z(k-2) -> p(k-2) ---
        if (k >= 3 && w == 0) {
            unsigned par2 = ((unsigned)(k & 1)) << 8;   // (k-2)&1 == k&1
            float u0, u1;
            asm volatile("ld.shared.f32 %0,[%1];" : "=f"(u0) : "r"(spb + par2 + 4u * lane));
            asm volatile("ld.shared.f32 %0,[%1];" : "=f"(u1) : "r"(spb + par2 + 4u * (lane + 32)));
            Pp[(size_t)(k - 2) * 32 + lane] = u0 + u1 - hb;
        }
        __syncthreads();
    }

    // drain 1: partial of z(ITERS) (in buf ITERS&1 = 0), combine p(ITERS-1)
    {
        ull pa0 = 0ull, pa1 = 0ull, pa2 = 0ull, pa3 = 0ull;
        unsigned zb = szb + (((unsigned)(ITERS & 1)) << 8) + ((unsigned)w << 7);
#pragma unroll
        for (int i = 0; i < 4; i++) {
            ull z0, z1;
            asm volatile("ld.shared.v2.b64 {%0,%1},[%2];"
                         : "=l"(z0), "=l"(z1) : "r"(zb + 32u * i));
            FMA2(pa0, hv[4 * i + 0], z0);
            FMA2(pa1, hv[4 * i + 1], z1);
            ull z2, z3;
            asm volatile("ld.shared.v2.b64 {%0,%1},[%2];"
                         : "=l"(z2), "=l"(z3) : "r"(zb + 32u * i + 16u));
            FMA2(pa2, hv[4 * i + 2], z2);
            FMA2(pa3, hv[4 * i + 3], z3);
        }
        ull q0, q1;
        asm("add.rn.f32x2 %0,%1,%2;" : "=l"(q0) : "l"(pa0), "l"(pa1));
        asm("add.rn.f32x2 %0,%1,%2;" : "=l"(q1) : "l"(pa2), "l"(pa3));
        float part = pairsum2(q0, q1);
        unsigned par = ((unsigned)(ITERS & 1)) << 8;
        asm volatile("st.shared.f32 [%0], %1;" :: "r"(spb + par + r4), "f"(part));

        if (w == 0) {
            unsigned par1 = ((unsigned)((ITERS - 1) & 1)) << 8;
            float u0, u1;
            asm volatile("ld.shared.f32 %0,[%1];" : "=f"(u0) : "r"(spb + par1 + 4u * lane));
            asm volatile("ld.shared.f32 %0,[%1];" : "=f"(u1) : "r"(spb + par1 + 4u * (lane + 32)));
            Pp[(size_t)(ITERS - 1) * 32 + lane] = u0 + u1 - hb;
        }
        __syncthreads();
    }
    // drain 2: combine p(ITERS)
    if (w == 0) {
        unsigned par = ((unsigned)(ITERS & 1)) << 8;
        float u0, u1;
        asm volatile("ld.shared.f32 %0,[%1];" : "=f"(u0) : "r"(spb + par + 4u * lane));
        asm volatile("ld.shared.f32 %0,[%1];" : "=f"(u1) : "r"(spb + par + 4u * (lane + 32)));
        Pp[(size_t)ITERS * 32 + lane] = u0 + u1 - hb;
    }
}

extern "C" void kernel_launch(void* const* d_in, const int* in_sizes, int n_in,
                              void* d_out, int out_size) {
    const float *q = nullptr, *b = nullptr, *P = nullptr, *H = nullptr;
    for (int i = 0; i < n_in; i++) {
        switch (in_sizes[i]) {
            case BSZ * NDIM:  q = (const float*)d_in[i]; break;  // 16384
            case BSZ * MDIM:  b = (const float*)d_in[i]; break;  // 32768
            case NDIM * NDIM: P = (const float*)d_in[i]; break;  // 1024
            case MDIM * NDIM: H = (const float*)d_in[i]; break;  // 2048
            default: break;                                      // iters ignored
        }
    }
    setup_kernel<<<1, 256>>>(P, H);
    solve_kernel<<<BSZ, 64>>>(q, b, (float*)d_out);
}

// round 12
// speedup vs baseline: 1.1448x; 1.1448x over previous
#include <cuda_runtime.h>

// QPSolver: N=32, M=64, BS=512, ITERS=1000, ALPHA=BETA=1
// Out layout (float32): Xs (512,1001,128) then primal_sols (512,1001,32).

#define BSZ   512
#define NDIM  32
#define MDIM  64
#define ITERS 1000

typedef unsigned long long ull;

__device__ __align__(16) float gD[MDIM * MDIM];      // D = H P^-1 H^T
__device__ __align__(16) float gHinv[NDIM * MDIM];   // pinv(H) (32x64)
__device__ __align__(16) float gWq[NDIM * MDIM];     // P^-1 H^T (32x64)
__device__ float gC;                                 // 1/lambda_max(D)

#define FMA2(acc, x, y) asm("fma.rn.f32x2 %0,%1,%2,%0;" : "+l"(acc) : "l"(x), "l"(y))
#define MUL2(d, x, y)   asm("mul.rn.f32x2 %0,%1,%2;" : "=l"(d) : "l"(x), "l"(y))

__device__ __forceinline__ float red4(ull a0, ull a1, ull a2, ull a3) {
    ull s0, s1, s;
    asm("add.rn.f32x2 %0,%1,%2;" : "=l"(s0) : "l"(a0), "l"(a1));
    asm("add.rn.f32x2 %0,%1,%2;" : "=l"(s1) : "l"(a2), "l"(a3));
    asm("add.rn.f32x2 %0,%1,%2;" : "=l"(s)  : "l"(s0), "l"(s1));
    unsigned lo, hi;
    asm("mov.b64 {%0,%1},%2;" : "=r"(lo), "=r"(hi) : "l"(s));
    return __uint_as_float(lo) + __uint_as_float(hi);
}
__device__ __forceinline__ ull dup2(float a) {
    ull r; asm("mov.b64 %0,{%1,%1};" : "=l"(r) : "f"(a)); return r;
}

// ---------------------------------------------------------------------------
// Warp-scope Gauss-Jordan on a 32 x 96 system, rows in registers, shfl
// broadcast, NO barriers, NO pivoting (SPD left block). Lane l holds row l.
// ---------------------------------------------------------------------------
__device__ __forceinline__ void gj_warp(float a[96], int lane) {
    for (int c = 0; c < 32; c++) {
        float myc = 0.0f;
#pragma unroll
        for (int j = 0; j < 32; j++) if (j == c) myc = a[j];
        float pv = __shfl_sync(0xffffffffu, myc, c);
        float inv = 1.0f / pv;
        float f = myc * inv;
        bool isp = (lane == c);
#pragma unroll
        for (int j = 0; j < 96; j++) {
            float pr = __shfl_sync(0xffffffffu, a[j], c);
            a[j] = isp ? pr * inv : fmaf(-f, pr, a[j]);
        }
    }
}

// ---------------------------------------------------------------------------
// Setup (1 block, 256 threads):
//   warp0: Wq = P^-1 H^T (GJ);  warp1: Hinv = (H^T H)^-1 H^T (GJ)
//   all:   D = H Wq  -> gD
//   warp0: B = Wq H (32x32, same nonzero spectrum AND same power-traces as D)
//          -> 5 trace-normalized squarings + 16 power iters -> gC
// ---------------------------------------------------------------------------
__global__ void __launch_bounds__(256) setup_kernel(
    const float* __restrict__ P, const float* __restrict__ H)
{
    __shared__ __align__(16) float sH[2048];     // H (64x32)
    __shared__ __align__(16) float sWq[2048];    // Wq (32x64)
    __shared__ __align__(16) float sB[2][32 * 34]; // B buffers, pitch 34
    __shared__ float sV[32];

    int t = threadIdx.x, lane = t & 31, w = t >> 5;

    for (int i = t; i < 2048; i += 256) sH[i] = H[i];
    __syncthreads();

    if (w == 0) {
        // solve P * Wq = H^T
        float a[96];
#pragma unroll
        for (int j = 0; j < 32; j++) a[j] = P[lane * 32 + j];
#pragma unroll
        for (int j = 0; j < 64; j++) a[32 + j] = sH[j * 32 + lane];
        gj_warp(a, lane);
#pragma unroll
        for (int j = 0; j < 64; j++) {
            sWq[lane * 64 + j] = a[32 + j];
            gWq[lane * 64 + j] = a[32 + j];
        }
    } else if (w == 1) {
        // G = H^T H, then solve G * Hinv = H^T
        ull acc[16];
#pragma unroll
        for (int j = 0; j < 16; j++) acc[j] = 0ull;
        for (int kk = 0; kk < 64; kk++) {
            ull hl = dup2(sH[kk * 32 + lane]);
            const ull* hr = (const ull*)(sH + kk * 32);
#pragma unroll
            for (int j = 0; j < 16; j++) FMA2(acc[j], hl, hr[j]);
        }
        float a[96];
#pragma unroll
        for (int j = 0; j < 16; j++) {
            unsigned lo, hi;
            asm("mov.b64 {%0,%1},%2;" : "=r"(lo), "=r"(hi) : "l"(acc[j]));
            a[2 * j] = __uint_as_float(lo);
            a[2 * j + 1] = __uint_as_float(hi);
        }
#pragma unroll
        for (int j = 0; j < 64; j++) a[32 + j] = sH[j * 32 + lane];
        gj_warp(a, lane);
#pragma unroll
        for (int j = 0; j < 64; j++) gHinv[lane * 64 + j] = a[32 + j];
    }
    __syncthreads();

    // D = H * Wq (64x64) -> gD
    {
        int r = t >> 2, cb = (t & 3) * 8;
        ull acc[8];
#pragma unroll
        for (int j = 0; j < 8; j++) acc[j] = 0ull;
        for (int kk = 0; kk < 32; kk++) {
            ull ap = dup2(sH[r * 32 + kk]);
            const ull* rw = (const ull*)(sWq + kk * 64);
#pragma unroll
            for (int j = 0; j < 8; j++) FMA2(acc[j], ap, rw[cb + j]);
        }
        ull* grow = (ull*)(gD + r * 64);
#pragma unroll
        for (int j = 0; j < 8; j++) grow[cb + j] = acc[j];
    }

    // warp0: eigen path on B = Wq @ H (32x32)
    if (w == 0) {
        float ts[6];
        // B[lane][j] = sum_k Wq[lane,k] * H[k,j]
        {
            ull bacc[16];
#pragma unroll
            for (int j = 0; j < 16; j++) bacc[j] = 0ull;
            for (int k = 0; k < 64; k++) {
                ull ap = dup2(sWq[lane * 64 + k]);
                const ull* hr = (const ull*)(sH + k * 32);
#pragma unroll
                for (int j = 0; j < 16; j++) FMA2(bacc[j], ap, hr[j]);
            }
            ull* dr = (ull*)(sB[0] + lane * 34);
#pragma unroll
            for (int j = 0; j < 16; j++) dr[j] = bacc[j];
        }
        __syncwarp();
        // trace + normalize in place
        {
            float tr = sB[0][lane * 34 + lane];
            for (int o = 16; o; o >>= 1) tr += __shfl_xor_sync(0xffffffffu, tr, o);
            ts[0] = tr;
            ull iv = dup2(1.0f / tr);
            ull* dr = (ull*)(sB[0] + lane * 34);
#pragma unroll
            for (int j = 0; j < 16; j++) { ull v = dr[j]; MUL2(v, v, iv); dr[j] = v; }
        }
        __syncwarp();
        // 5 trace-normalized squarings (rolled k-loop; small code)
        for (int s = 1; s <= 5; s++) {
            const float* src = sB[(s - 1) & 1];
            float* dst = sB[s & 1];
            ull cacc[16];
#pragma unroll
            for (int j = 0; j < 16; j++) cacc[j] = 0ull;
            for (int k = 0; k < 32; k++) {
                ull ap = dup2(src[lane * 34 + k]);
                const ull* rw = (const ull*)(src + k * 34);
#pragma unroll
                for (int j = 0; j < 16; j++) FMA2(cacc[j], ap, rw[j]);
            }
            ull* dr = (ull*)(dst + lane * 34);
#pragma unroll
            for (int j = 0; j < 16; j++) dr[j] = cacc[j];
            __syncwarp();
            float tr = dst[lane * 34 + lane];
            for (int o = 16; o; o >>= 1) tr += __shfl_xor_sync(0xffffffffu, tr, o);
            ts[s] = tr;
            ull iv = dup2(1.0f / tr);
#pragma unroll
            for (int j = 0; j < 16; j++) { ull v = dr[j]; MUL2(v, v, iv); dr[j] = v; }
            __syncwarp();
        }
        // power iteration on B^32 (in sB[1])
        const float* Bs = sB[1];
        float v = 1.0f + 0.001f * (float)lane;
        sV[lane] = v;
        __syncwarp();
        float wv = 0.0f;
        for (int it = 0; it <= 16; it++) {
            wv = 0.0f;
            for (int k = 0; k < 32; k++) wv = fmaf(Bs[lane * 34 + k], sV[k], wv);
            if (it == 16) break;
            float m = fabsf(wv);
            for (int o = 16; o; o >>= 1) m = fmaxf(m, __shfl_xor_sync(0xffffffffu, m, o));
            v = wv * (1.0f / m);
            sV[lane] = v;
            __syncwarp();
        }
        float num = v * wv, den = v * v;
        for (int o = 16; o; o >>= 1) {
            num += __shfl_xor_sync(0xffffffffu, num, o);
            den += __shfl_xor_sync(0xffffffffu, den, o);
        }
        if (lane == 0) {
            double lam = (double)num / (double)den;
            for (int s = 5; s >= 1; s--) lam = sqrt((double)ts[s] * lam);
            gC = (float)(1.0 / ((double)ts[0] * lam));
        }
    }
}

// ---------------------------------------------------------------------------
// Solver: ONE warp per row, ZERO barriers in the hot loop (single-warp shared
// ops are program-ordered). Lane owns outputs r=lane and r=lane+32; D rows in
// 128 registers; y broadcast via shared double buffer.
//   y' = c*(D y + z) + mu ;  z' = relu(y + z - 2 y')
// Primal p(k-1) = Hinv z(k-1) - hb computed fully each iteration (Hinv from
// block-shared, pitch 68 conflict-free), lagging one step.
// ---------------------------------------------------------------------------
__global__ void __launch_bounds__(64) solve_kernel(
    const float* __restrict__ q, const float* __restrict__ b, float* __restrict__ out)
{
    __shared__ __align__(16) float sHinv[32 * 68];   // 8704 B, shared by both warps
    __shared__ __align__(16) float sy[2][2][64];     // [warp][buf][64]
    __shared__ __align__(16) float sz[2][2][64];

    int t = threadIdx.x, lane = t & 31, w = t >> 5;
    int row = blockIdx.x * 2 + w;

    for (int i = t; i < 2048; i += 64)
        sHinv[(i >> 6) * 68 + (i & 63)] = gHinv[i];
    __syncthreads();                                  // only barrier

    float c = gC;

    // D rows lane and lane+32 resident (64 ull = 128 regs)
    ull dA2[32], dB2[32];
    const ull* gD2 = (const ull*)gD;
#pragma unroll
    for (int i = 0; i < 32; i++) {
        dA2[i] = gD2[lane * 32 + i];
        dB2[i] = gD2[(lane + 32) * 32 + i];
    }

    const float* qr = q + row * NDIM;
    const float* br = b + (size_t)row * MDIM;
    float mu0 = 0.0f, mu1 = 0.0f;
#pragma unroll
    for (int i = 0; i < 32; i++) {
        float qi = qr[i];
        mu0 = fmaf(qi, gWq[i * 64 + lane], mu0);
        mu1 = fmaf(qi, gWq[i * 64 + lane + 32], mu1);
    }
    mu0 = c * (mu0 - br[lane]);
    mu1 = c * (mu1 - br[lane + 32]);

    // hb = Hinv[lane] . b_row
    float hb = 0.0f;
#pragma unroll
    for (int j = 0; j < 64; j++) hb = fmaf(sHinv[lane * 68 + j], br[j], hb);

    float* Xp = out + (size_t)row * (ITERS + 1) * 128;
    float* Pp = out + (size_t)BSZ * (ITERS + 1) * 128 + (size_t)row * (ITERS + 1) * 32;

    // k = 0 outputs (p(0) = -hb is produced by the shadow at k=1 from z(0)=0)
    Xp[lane] = 0.0f; Xp[lane + 32] = 0.0f; Xp[lane + 64] = 0.0f; Xp[lane + 96] = 0.0f;

    unsigned syb = (unsigned)__cvta_generic_to_shared(&sy[w][0][0]);
    unsigned szb = (unsigned)__cvta_generic_to_shared(&sz[w][0][0]);
    unsigned hvb = (unsigned)__cvta_generic_to_shared(&sHinv[0]) + (unsigned)lane * 272u;
    unsigned l4 = 4u * (unsigned)lane;

    // init buffer 0 to zeros
    asm volatile("st.shared.f32 [%0], %1;" :: "r"(syb + l4), "f"(0.0f));
    asm volatile("st.shared.f32 [%0], %1;" :: "r"(syb + l4 + 128u), "f"(0.0f));
    asm volatile("st.shared.f32 [%0], %1;" :: "r"(szb + l4), "f"(0.0f));
    asm volatile("st.shared.f32 [%0], %1;" :: "r"(szb + l4 + 128u), "f"(0.0f));
    __syncwarp();

    float y0 = 0.0f, y1 = 0.0f, z0 = 0.0f, z1 = 0.0f;
    float* xk = Xp + 128;

    for (int k = 1; k <= ITERS; k++) {
        unsigned rbo = ((unsigned)((k & 1) ^ 1)) << 8;   // buf (k-1)&1
        unsigned wbo = ((unsigned)(k & 1)) << 8;         // buf k&1

        // --- y-matvec: both D rows against broadcast y(k-1) ---
        ull aA0 = 0ull, aA1 = 0ull, aA2 = 0ull, aA3 = 0ull;
        ull aB0 = 0ull, aB1 = 0ull, aB2 = 0ull, aB3 = 0ull;
#pragma unroll
        for (int i = 0; i < 8; i++) {
            ull p0, p1, p2, p3;
            asm volatile("ld.shared.v2.b64 {%0,%1},[%2];"
                         : "=l"(p0), "=l"(p1) : "r"(syb + rbo + 32u * i));
            asm volatile("ld.shared.v2.b64 {%0,%1},[%2];"
                         : "=l"(p2), "=l"(p3) : "r"(syb + rbo + 32u * i + 16u));
            FMA2(aA0, dA2[4 * i + 0], p0);
            FMA2(aA1, dA2[4 * i + 1], p1);
            FMA2(aA2, dA2[4 * i + 2], p2);
            FMA2(aA3, dA2[4 * i + 3], p3);
            FMA2(aB0, dB2[4 * i + 0], p0);
            FMA2(aB1, dB2[4 * i + 1], p1);
            FMA2(aB2, dB2[4 * i + 2], p2);
            FMA2(aB3, dB2[4 * i + 3], p3);
        }
        float w0 = red4(aA0, aA1, aA2, aA3);
        float w1 = red4(aB0, aB1, aB2, aB3);

        float ny0 = fmaf(c, w0 + z0, mu0);
        float ny1 = fmaf(c, w1 + z1, mu1);
        float nz0 = fmaxf(fmaf(-2.0f, ny0, y0 + z0), 0.0f);
        float nz1 = fmaxf(fmaf(-2.0f, ny1, y1 + z1), 0.0f);

        asm volatile("st.shared.f32 [%0], %1;" :: "r"(syb + wbo + l4),        "f"(ny0));
        asm volatile("st.shared.f32 [%0], %1;" :: "r"(syb + wbo + l4 + 128u), "f"(ny1));
        asm volatile("st.shared.f32 [%0], %1;" :: "r"(szb + wbo + l4),        "f"(nz0));
        asm volatile("st.shared.f32 [%0], %1;" :: "r"(szb + wbo + l4 + 128u), "f"(nz1));
        y0 = ny0; y1 = ny1; z0 = nz0; z1 = nz1;

        xk[lane] = y0; xk[lane + 32] = y1; xk[lane + 64] = z0; xk[lane + 96] = z1;
        xk += 128;

        // --- shadow: p(k-1) = Hinv[lane] . z(k-1) - hb  (z(k-1) in buf rbo) ---
        {
            ull pa0 = 0ull, pa1 = 0ull, pa2 = 0ull, pa3 = 0ull;
#pragma unroll
            for (int i = 0; i < 8; i++) {
                ull h0, h1, zp0, zp1;
                asm volatile("ld.shared.v2.b64 {%0,%1},[%2];"
                             : "=l"(h0), "=l"(h1) : "r"(hvb + 16u * (2 * i)));
                asm volatile("ld.shared.v2.b64 {%0,%1},[%2];"
                             : "=l"(zp0), "=l"(zp1) : "r"(szb + rbo + 16u * (2 * i)));
                FMA2(pa0, h0, zp0);
                FMA2(pa1, h1, zp1);
                ull h2, h3, zp2, zp3;
                asm volatile("ld.shared.v2.b64 {%0,%1},[%2];"
                             : "=l"(h2), "=l"(h3) : "r"(hvb + 16u * (2 * i + 1)));
                asm volatile("ld.shared.v2.b64 {%0,%1},[%2];"
                             : "=l"(zp2), "=l"(zp3) : "r"(szb + rbo + 16u * (2 * i + 1)));
                FMA2(pa2, h2, zp2);
                FMA2(pa3, h3, zp3);
            }
            Pp[(size_t)(k - 1) * 32 + lane] = red4(pa0, pa1, pa2, pa3) - hb;
        }
    }

    // drain: p(ITERS) from z buf (ITERS&1) = 0
    {
        unsigned rbo = ((unsigned)(ITERS & 1)) << 8;
        ull pa0 = 0ull, pa1 = 0ull, pa2 = 0ull, pa3 = 0ull;
#pragma unroll
        for (int i = 0; i < 16; i++) {
            ull h0, h1, zp0, zp1;
            asm volatile("ld.shared.v2.b64 {%0,%1},[%2];"
                         : "=l"(h0), "=l"(h1) : "r"(hvb + 16u * i));
            asm volatile("ld.shared.v2.b64 {%0,%1},[%2];"
                         : "=l"(zp0), "=l"(zp1) : "r"(szb + rbo + 16u * i));
            if (i & 1) { FMA2(pa2, h0, zp0); FMA2(pa3, h1, zp1); }
            else       { FMA2(pa0, h0, zp0); FMA2(pa1, h1, zp1); }
        }
        Pp[(size_t)ITERS * 32 + lane] = red4(pa0, pa1, pa2, pa3) - hb;
    }
}

extern "C" void kernel_launch(void* const* d_in, const int* in_sizes, int n_in,
                              void* d_out, int out_size) {
    const float *q = nullptr, *b = nullptr, *P = nullptr, *H = nullptr;
    for (int i = 0; i < n_in; i++) {
        switch (in_sizes[i]) {
            case BSZ * NDIM:  q = (const float*)d_in[i]; break;  // 16384
            case BSZ * MDIM:  b = (const float*)d_in[i]; break;  // 32768
            case NDIM * NDIM: P = (const float*)d_in[i]; break;  // 1024
            case MDIM * NDIM: H = (const float*)d_in[i]; break;  // 2048
            default: break;                                      // iters ignored
        }
    }
    setup_kernel<<<1, 256>>>(P, H);
    solve_kernel<<<BSZ / 2, 64>>>(q, b, (float*)d_out);
}

// round 13
// speedup vs baseline: 1.3721x; 1.1986x over previous
#include <cuda_runtime.h>

// QPSolver: N=32, M=64, BS=512, ITERS=1000, ALPHA=BETA=1
// Out layout (float32): Xs (512,1001,128) then primal_sols (512,1001,32).

#define BSZ   512
#define NDIM  32
#define MDIM  64
#define ITERS 1000

typedef unsigned long long ull;

__device__ __align__(16) float gD[MDIM * MDIM];      // D = H P^-1 H^T
__device__ __align__(16) float gHinv[NDIM * MDIM];   // pinv(H) (32x64)
__device__ __align__(16) float gWq[NDIM * MDIM];     // P^-1 H^T (32x64)
__device__ float gC;                                 // 1/lambda_max(D)

#define FMA2(acc, x, y) asm("fma.rn.f32x2 %0,%1,%2,%0;" : "+l"(acc) : "l"(x), "l"(y))
#define MUL2(d, x, y)   asm("mul.rn.f32x2 %0,%1,%2;" : "=l"(d) : "l"(x), "l"(y))

__device__ __forceinline__ float red4(ull a0, ull a1, ull a2, ull a3) {
    ull s0, s1, s;
    asm("add.rn.f32x2 %0,%1,%2;" : "=l"(s0) : "l"(a0), "l"(a1));
    asm("add.rn.f32x2 %0,%1,%2;" : "=l"(s1) : "l"(a2), "l"(a3));
    asm("add.rn.f32x2 %0,%1,%2;" : "=l"(s)  : "l"(s0), "l"(s1));
    unsigned lo, hi;
    asm("mov.b64 {%0,%1},%2;" : "=r"(lo), "=r"(hi) : "l"(s));
    return __uint_as_float(lo) + __uint_as_float(hi);
}
__device__ __forceinline__ ull dup2(float a) {
    ull r; asm("mov.b64 %0,{%1,%1};" : "=l"(r) : "f"(a)); return r;
}

// ---------------------------------------------------------------------------
// Warp-scope Gauss-Jordan on a 32 x 96 system, rows in registers, shfl
// broadcast, NO barriers, NO pivoting (SPD left block). Lane l holds row l.
// ---------------------------------------------------------------------------
__device__ __forceinline__ void gj_warp(float a[96], int lane) {
    for (int c = 0; c < 32; c++) {
        float myc = 0.0f;
#pragma unroll
        for (int j = 0; j < 32; j++) if (j == c) myc = a[j];
        float pv = __shfl_sync(0xffffffffu, myc, c);
        float inv = 1.0f / pv;
        float f = myc * inv;
        bool isp = (lane == c);
#pragma unroll
        for (int j = 0; j < 96; j++) {
            float pr = __shfl_sync(0xffffffffu, a[j], c);
            a[j] = isp ? pr * inv : fmaf(-f, pr, a[j]);
        }
    }
}

// ---------------------------------------------------------------------------
// Setup (1 block, 256 threads):
//   warp0: Wq = P^-1 H^T (GJ);  warp1: Hinv = (H^T H)^-1 H^T (GJ)
//   all:   D = H Wq  -> gD
//   warp0: B = Wq H (32x32, same nonzero spectrum AND same power-traces as D)
//          -> 5 trace-normalized squarings + 16 power iters -> gC
// ---------------------------------------------------------------------------
__global__ void __launch_bounds__(256) setup_kernel(
    const float* __restrict__ P, const float* __restrict__ H)
{
    __shared__ __align__(16) float sH[2048];       // H (64x32)
    __shared__ __align__(16) float sWq[2048];      // Wq (32x64)
    __shared__ __align__(16) float sB[2][32 * 34]; // B buffers, pitch 34
    __shared__ float sV[32];

    int t = threadIdx.x, lane = t & 31, w = t >> 5;

    for (int i = t; i < 2048; i += 256) sH[i] = H[i];
    __syncthreads();

    if (w == 0) {
        float a[96];
#pragma unroll
        for (int j = 0; j < 32; j++) a[j] = P[lane * 32 + j];
#pragma unroll
        for (int j = 0; j < 64; j++) a[32 + j] = sH[j * 32 + lane];
        gj_warp(a, lane);
#pragma unroll
        for (int j = 0; j < 64; j++) {
            sWq[lane * 64 + j] = a[32 + j];
            gWq[lane * 64 + j] = a[32 + j];
        }
    } else if (w == 1) {
        ull acc[16];
#pragma unroll
        for (int j = 0; j < 16; j++) acc[j] = 0ull;
        for (int kk = 0; kk < 64; kk++) {
            ull hl = dup2(sH[kk * 32 + lane]);
            const ull* hr = (const ull*)(sH + kk * 32);
#pragma unroll
            for (int j = 0; j < 16; j++) FMA2(acc[j], hl, hr[j]);
        }
        float a[96];
#pragma unroll
        for (int j = 0; j < 16; j++) {
            unsigned lo, hi;
            asm("mov.b64 {%0,%1},%2;" : "=r"(lo), "=r"(hi) : "l"(acc[j]));
            a[2 * j] = __uint_as_float(lo);
            a[2 * j + 1] = __uint_as_float(hi);
        }
#pragma unroll
        for (int j = 0; j < 64; j++) a[32 + j] = sH[j * 32 + lane];
        gj_warp(a, lane);
#pragma unroll
        for (int j = 0; j < 64; j++) gHinv[lane * 64 + j] = a[32 + j];
    }
    __syncthreads();

    // D = H * Wq (64x64) -> gD
    {
        int r = t >> 2, cb = (t & 3) * 8;
        ull acc[8];
#pragma unroll
        for (int j = 0; j < 8; j++) acc[j] = 0ull;
        for (int kk = 0; kk < 32; kk++) {
            ull ap = dup2(sH[r * 32 + kk]);
            const ull* rw = (const ull*)(sWq + kk * 64);
#pragma unroll
            for (int j = 0; j < 8; j++) FMA2(acc[j], ap, rw[cb + j]);
        }
        ull* grow = (ull*)(gD + r * 64);
#pragma unroll
        for (int j = 0; j < 8; j++) grow[cb + j] = acc[j];
    }

    // warp0: eigen path on B = Wq @ H (32x32)
    if (w == 0) {
        float ts[6];
        {
            ull bacc[16];
#pragma unroll
            for (int j = 0; j < 16; j++) bacc[j] = 0ull;
            for (int k = 0; k < 64; k++) {
                ull ap = dup2(sWq[lane * 64 + k]);
                const ull* hr = (const ull*)(sH + k * 32);
#pragma unroll
                for (int j = 0; j < 16; j++) FMA2(bacc[j], ap, hr[j]);
            }
            ull* dr = (ull*)(sB[0] + lane * 34);
#pragma unroll
            for (int j = 0; j < 16; j++) dr[j] = bacc[j];
        }
        __syncwarp();
        {
            float tr = sB[0][lane * 34 + lane];
            for (int o = 16; o; o >>= 1) tr += __shfl_xor_sync(0xffffffffu, tr, o);
            ts[0] = tr;
            ull iv = dup2(1.0f / tr);
            ull* dr = (ull*)(sB[0] + lane * 34);
#pragma unroll
            for (int j = 0; j < 16; j++) { ull v = dr[j]; MUL2(v, v, iv); dr[j] = v; }
        }
        __syncwarp();
        for (int s = 1; s <= 5; s++) {
            const float* src = sB[(s - 1) & 1];
            float* dst = sB[s & 1];
            ull cacc[16];
#pragma unroll
            for (int j = 0; j < 16; j++) cacc[j] = 0ull;
            for (int k = 0; k < 32; k++) {
                ull ap = dup2(src[lane * 34 + k]);
                const ull* rw = (const ull*)(src + k * 34);
#pragma unroll
                for (int j = 0; j < 16; j++) FMA2(cacc[j], ap, rw[j]);
            }
            ull* dr = (ull*)(dst + lane * 34);
#pragma unroll
            for (int j = 0; j < 16; j++) dr[j] = cacc[j];
            __syncwarp();
            float tr = dst[lane * 34 + lane];
            for (int o = 16; o; o >>= 1) tr += __shfl_xor_sync(0xffffffffu, tr, o);
            ts[s] = tr;
            ull iv = dup2(1.0f / tr);
#pragma unroll
            for (int j = 0; j < 16; j++) { ull v = dr[j]; MUL2(v, v, iv); dr[j] = v; }
            __syncwarp();
        }
        const float* Bs = sB[1];
        float v = 1.0f + 0.001f * (float)lane;
        sV[lane] = v;
        __syncwarp();
        float wv = 0.0f;
        for (int it = 0; it <= 16; it++) {
            wv = 0.0f;
            for (int k = 0; k < 32; k++) wv = fmaf(Bs[lane * 34 + k], sV[k], wv);
            if (it == 16) break;
            float m = fabsf(wv);
            for (int o = 16; o; o >>= 1) m = fmaxf(m, __shfl_xor_sync(0xffffffffu, m, o));
            v = wv * (1.0f / m);
            sV[lane] = v;
            __syncwarp();
        }
        float num = v * wv, den = v * v;
        for (int o = 16; o; o >>= 1) {
            num += __shfl_xor_sync(0xffffffffu, num, o);
            den += __shfl_xor_sync(0xffffffffu, den, o);
        }
        if (lane == 0) {
            double lam = (double)num / (double)den;
            for (int s = 5; s >= 1; s--) lam = sqrt((double)ts[s] * lam);
            gC = (float)(1.0 / ((double)ts[0] * lam));
        }
    }
}

// ---------------------------------------------------------------------------
// Solver: ONE warp per row, 4 rows per block (128 thr -> exactly 1 warp per
// SMSP), zero barriers in the hot loop.  Lane owns outputs lane & lane+32.
//   y' = c*(D y + z) + mu ;  z' = relu(y + z - 2 y')
// D rows in 128 regs; Hinv[lane][0:32] in 32 regs; Hinv[lane][32:64] from
// shared (pitch 68, conflict-free). y/z broadcast via per-warp double buffer.
// Primal p(k-1) = Hinv z(k-1) - hb lags one step in the loop.
// ---------------------------------------------------------------------------
__global__ void __launch_bounds__(128, 1) solve_kernel(
    const float* __restrict__ q, const float* __restrict__ b, float* __restrict__ out)
{
    __shared__ __align__(16) float sHinv[32 * 68];   // full Hinv, back half used
    __shared__ __align__(16) float sy[4][2][64];
    __shared__ __align__(16) float sz[4][2][64];

    int t = threadIdx.x, lane = t & 31, w = t >> 5;
    int row = blockIdx.x * 4 + w;

    for (int i = t; i < 2048; i += 128)
        sHinv[(i >> 6) * 68 + (i & 63)] = gHinv[i];
    __syncthreads();                                  // only barrier

    float c = gC;

    // D rows lane and lane+32 resident (64 ull = 128 regs)
    ull dA2[32], dB2[32];
    const ull* gD2 = (const ull*)gD;
#pragma unroll
    for (int i = 0; i < 32; i++) {
        dA2[i] = gD2[lane * 32 + i];
        dB2[i] = gD2[(lane + 32) * 32 + i];
    }
    // Hinv front half (k = 0..31) resident (16 ull = 32 regs)
    ull hv[16];
    const ull* gH2 = (const ull*)gHinv;
#pragma unroll
    for (int i = 0; i < 16; i++) hv[i] = gH2[lane * 32 + i];

    const float* qr = q + row * NDIM;
    const float* br = b + (size_t)row * MDIM;
    float mu0 = 0.0f, mu1 = 0.0f;
#pragma unroll
    for (int i = 0; i < 32; i++) {
        float qi = qr[i];
        mu0 = fmaf(qi, gWq[i * 64 + lane], mu0);
        mu1 = fmaf(qi, gWq[i * 64 + lane + 32], mu1);
    }
    mu0 = c * (mu0 - br[lane]);
    mu1 = c * (mu1 - br[lane + 32]);

    // hb = Hinv[lane] . b_row  (front half from regs, back half from shared)
    float hb;
    {
        const ull* b2 = (const ull*)br;
        ull a0 = 0ull, a1 = 0ull, a2 = 0ull, a3 = 0ull;
#pragma unroll
        for (int i = 0; i < 8; i++) {
            FMA2(a0, hv[2 * i], b2[2 * i]);
            FMA2(a1, hv[2 * i + 1], b2[2 * i + 1]);
        }
        const ull* hs = (const ull*)(sHinv + lane * 68 + 32);
#pragma unroll
        for (int i = 0; i < 8; i++) {
            FMA2(a2, hs[2 * i], b2[16 + 2 * i]);
            FMA2(a3, hs[2 * i + 1], b2[16 + 2 * i + 1]);
        }
        hb = red4(a0, a1, a2, a3);
    }

    float* Xp = out + (size_t)row * (ITERS + 1) * 128;
    float* Pp = out + (size_t)BSZ * (ITERS + 1) * 128 + (size_t)row * (ITERS + 1) * 32;

    // k = 0 outputs (p(0) comes from the shadow at k=1 with z(0)=0)
    Xp[lane] = 0.0f; Xp[lane + 32] = 0.0f; Xp[lane + 64] = 0.0f; Xp[lane + 96] = 0.0f;

    unsigned syb = (unsigned)__cvta_generic_to_shared(&sy[w][0][0]);
    unsigned szb = (unsigned)__cvta_generic_to_shared(&sz[w][0][0]);
    unsigned hvb = (unsigned)__cvta_generic_to_shared(&sHinv[0]) + (unsigned)lane * 272u + 128u;
    unsigned l4 = 4u * (unsigned)lane;

    asm volatile("st.shared.f32 [%0], %1;" :: "r"(syb + l4), "f"(0.0f));
    asm volatile("st.shared.f32 [%0], %1;" :: "r"(syb + l4 + 128u), "f"(0.0f));
    asm volatile("st.shared.f32 [%0], %1;" :: "r"(szb + l4), "f"(0.0f));
    asm volatile("st.shared.f32 [%0], %1;" :: "r"(szb + l4 + 128u), "f"(0.0f));
    __syncwarp();

    float y0 = 0.0f, y1 = 0.0f, z0 = 0.0f, z1 = 0.0f;
    float* xk = Xp + 128;

    for (int k = 1; k <= ITERS; k++) {
        unsigned rbo = ((unsigned)((k & 1) ^ 1)) << 8;   // buf (k-1)&1
        unsigned wbo = ((unsigned)(k & 1)) << 8;         // buf k&1

        // --- y-matvec: both D rows vs broadcast y(k-1) ---
        ull aA0 = 0ull, aA1 = 0ull, aB0 = 0ull, aB1 = 0ull;
#pragma unroll
        for (int i = 0; i < 8; i++) {
            ull p0, p1, p2, p3;
            asm volatile("ld.shared.v2.b64 {%0,%1},[%2];"
                         : "=l"(p0), "=l"(p1) : "r"(syb + rbo + 32u * i));
            asm volatile("ld.shared.v2.b64 {%0,%1},[%2];"
                         : "=l"(p2), "=l"(p3) : "r"(syb + rbo + 32u * i + 16u));
            FMA2(aA0, dA2[4 * i + 0], p0);
            FMA2(aA1, dA2[4 * i + 1], p1);
            FMA2(aA0, dA2[4 * i + 2], p2);
            FMA2(aA1, dA2[4 * i + 3], p3);
            FMA2(aB0, dB2[4 * i + 0], p0);
            FMA2(aB1, dB2[4 * i + 1], p1);
            FMA2(aB0, dB2[4 * i + 2], p2);
            FMA2(aB1, dB2[4 * i + 3], p3);
        }
        float w0, w1;
        {
            ull sA, sB;
            asm("add.rn.f32x2 %0,%1,%2;" : "=l"(sA) : "l"(aA0), "l"(aA1));
            asm("add.rn.f32x2 %0,%1,%2;" : "=l"(sB) : "l"(aB0), "l"(aB1));
            unsigned lo, hi;
            asm("mov.b64 {%0,%1},%2;" : "=r"(lo), "=r"(hi) : "l"(sA));
            w0 = __uint_as_float(lo) + __uint_as_float(hi);
            asm("mov.b64 {%0,%1},%2;" : "=r"(lo), "=r"(hi) : "l"(sB));
            w1 = __uint_as_float(lo) + __uint_as_float(hi);
        }

        float ny0 = fmaf(c, w0 + z0, mu0);
        float ny1 = fmaf(c, w1 + z1, mu1);
        float nz0 = fmaxf(fmaf(-2.0f, ny0, y0 + z0), 0.0f);
        float nz1 = fmaxf(fmaf(-2.0f, ny1, y1 + z1), 0.0f);

        asm volatile("st.shared.f32 [%0], %1;" :: "r"(syb + wbo + l4),        "f"(ny0));
        asm volatile("st.shared.f32 [%0], %1;" :: "r"(syb + wbo + l4 + 128u), "f"(ny1));
        asm volatile("st.shared.f32 [%0], %1;" :: "r"(szb + wbo + l4),        "f"(nz0));
        asm volatile("st.shared.f32 [%0], %1;" :: "r"(szb + wbo + l4 + 128u), "f"(nz1));
        y0 = ny0; y1 = ny1; z0 = nz0; z1 = nz1;

        xk[lane] = y0; xk[lane + 32] = y1; xk[lane + 64] = z0; xk[lane + 96] = z1;
        xk += 128;

        // --- shadow: p(k-1) = Hinv[lane] . z(k-1) - hb ---
        {
            ull pa0 = 0ull, pa1 = 0ull, pa2 = 0ull, pa3 = 0ull;
            // front half: Hinv regs x broadcast z[0:32]
#pragma unroll
            for (int i = 0; i < 8; i++) {
                ull zp0, zp1;
                asm volatile("ld.shared.v2.b64 {%0,%1},[%2];"
                             : "=l"(zp0), "=l"(zp1) : "r"(szb + rbo + 16u * i));
                FMA2(pa0, hv[2 * i], zp0);
                FMA2(pa1, hv[2 * i + 1], zp1);
            }
            // back half: Hinv shared (per-lane, conflict-free) x broadcast z[32:64]
#pragma unroll
            for (int i = 0; i < 8; i++) {
                ull h0, h1, zp0, zp1;
                asm volatile("ld.shared.v2.b64 {%0,%1},[%2];"
                             : "=l"(h0), "=l"(h1) : "r"(hvb + 16u * i));
                asm volatile("ld.shared.v2.b64 {%0,%1},[%2];"
                             : "=l"(zp0), "=l"(zp1) : "r"(szb + rbo + 128u + 16u * i));
                FMA2(pa2, h0, zp0);
                FMA2(pa3, h1, zp1);
            }
            Pp[(size_t)(k - 1) * 32 + lane] = red4(pa0, pa1, pa2, pa3) - hb;
        }
    }

    // drain: p(ITERS) from z buf (ITERS&1) = 0
    {
        unsigned rbo = ((unsigned)(ITERS & 1)) << 8;
        ull pa0 = 0ull, pa1 = 0ull, pa2 = 0ull, pa3 = 0ull;
#pragma unroll
        for (int i = 0; i < 8; i++) {
            ull zp0, zp1;
            asm volatile("ld.shared.v2.b64 {%0,%1},[%2];"
                         : "=l"(zp0), "=l"(zp1) : "r"(szb + rbo + 16u * i));
            FMA2(pa0, hv[2 * i], zp0);
            FMA2(pa1, hv[2 * i + 1], zp1);
        }
#pragma unroll
        for (int i = 0; i < 8; i++) {
            ull h0, h1, zp0, zp1;
            asm volatile("ld.shared.v2.b64 {%0,%1},[%2];"
                         : "=l"(h0), "=l"(h1) : "r"(hvb + 16u * i));
            asm volatile("ld.shared.v2.b64 {%0,%1},[%2];"
                         : "=l"(zp0), "=l"(zp1) : "r"(szb + rbo + 128u + 16u * i));
            FMA2(pa2, h0, zp0);
            FMA2(pa3, h1, zp1);
        }
        Pp[(size_t)ITERS * 32 + lane] = red4(pa0, pa1, pa2, pa3) - hb;
    }
}

extern "C" void kernel_launch(void* const* d_in, const int* in_sizes, int n_in,
                              void* d_out, int out_size) {
    const float *q = nullptr, *b = nullptr, *P = nullptr, *H = nullptr;
    for (int i = 0; i < n_in; i++) {
        switch (in_sizes[i]) {
            case BSZ * NDIM:  q = (const float*)d_in[i]; break;  // 16384
            case BSZ * MDIM:  b = (const float*)d_in[i]; break;  // 32768
            case NDIM * NDIM: P = (const float*)d_in[i]; break;  // 1024
            case MDIM * NDIM: H = (const float*)d_in[i]; break;  // 2048
            default: break;                                      // iters ignored
        }
    }
    setup_kernel<<<1, 256>>>(P, H);
    solve_kernel<<<BSZ / 4, 128>>>(q, b, (float*)d_out);
}